// round 1
// baseline (speedup 1.0000x reference)
#include <cuda_runtime.h>

#define FULL 0xFFFFFFFFu

// feat[b][n] scratch (64*1024 floats). __device__ global = allowed scratch.
__device__ float g_feat[64 * 1024];

// Padded smem layout: insert 4 floats of pad per 32 elements (16B per 128B).
// pos(i) = i + 4*(i>>5). For float4 at element e (e%4==0): f4slot = (e>>2) + (e>>5).
__device__ __forceinline__ int spos(int i) { return i + ((i >> 5) << 2); }

__global__ __launch_bounds__(256) void conv_chain_kernel(
    const float* __restrict__ x,
    const float* __restrict__ w1, const float* __restrict__ b1,
    const float* __restrict__ w2, const float* __restrict__ b2,
    const float* __restrict__ w3, const float* __restrict__ b3)
{
    // 8 warps per block, one row (b,n) per warp.
    __shared__ float sm[8][1360];

    const int warp = threadIdx.x >> 5;
    const int lane = threadIdx.x & 31;
    const int row  = blockIdx.x * 8 + warp;   // row in [0, 65536)

    float* S  = sm[warp];
    float4* S4 = reinterpret_cast<float4*>(S);
    const float4* X4 = reinterpret_cast<const float4*>(x + (size_t)row * 1200);

    // ---- Stage row into padded smem (coalesced LDG.128, conflict-free STS.128)
    #pragma unroll
    for (int t = lane; t < 300; t += 32) {
        S4[t + (t >> 3)] = X4[t];
    }
    // zero-fill elems 1200..1203 (right pad region read by j=149 tail)
    if (lane < 4) S[spos(1200 + lane)] = 0.0f;
    __syncwarp();

    // ---- conv1: K=10, stride=8, pad=1, out length 150, relu
    float W1[10];
    #pragma unroll
    for (int k = 0; k < 10; k++) W1[k] = __ldg(&w1[k]);
    const float B1 = __ldg(b1);

    float y[5];
    float carry = 0.0f;  // x[8*j - 1] carry across iterations (x[-1] = 0 pad)
    #pragma unroll
    for (int it = 0; it < 5; it++) {
        int j  = it * 32 + lane;
        int jj = j < 150 ? j : 149;        // clamp for inactive lanes (it==4)
        int e  = jj * 8;
        int f4i = (e >> 2) + (e >> 5);
        float4 a0 = S4[f4i];               // x[e .. e+3]
        float4 a1 = S4[f4i + 1];           // x[e+4 .. e+7]
        float  a2 = S[spos(e + 8)];        // x[e+8]

        // x[8j-1] = elem 8(j-1)+7 = previous lane's a1.w
        float xm1 = __shfl_up_sync(FULL, a1.w, 1);
        if (lane == 0) xm1 = carry;
        carry = __shfl_sync(FULL, a1.w, 31);

        float v = B1;
        v = fmaf(W1[0], xm1,  v);
        v = fmaf(W1[1], a0.x, v);
        v = fmaf(W1[2], a0.y, v);
        v = fmaf(W1[3], a0.z, v);
        v = fmaf(W1[4], a0.w, v);
        v = fmaf(W1[5], a1.x, v);
        v = fmaf(W1[6], a1.y, v);
        v = fmaf(W1[7], a1.z, v);
        v = fmaf(W1[8], a1.w, v);
        v = fmaf(W1[9], a2,   v);
        y[it] = fmaxf(v, 0.0f);
    }

    // ---- write y1 (150 vals) to smem scratch (reuse staging buffer)
    __syncwarp();
    #pragma unroll
    for (int it = 0; it < 5; it++) {
        int j = it * 32 + lane;
        if (j < 150) S[j] = y[it];
    }
    __syncwarp();

    // ---- maxpool k=5 s=5 (150 -> 30), relu no-op (values >= 0)
    float p = 0.0f;
    if (lane < 30) {
        p = S[5 * lane];
        #pragma unroll
        for (int k = 1; k < 5; k++) p = fmaxf(p, S[5 * lane + k]);
    }

    // ---- conv2: K=3 s=3 (30 -> 10), relu  (lanes 0..9 produce q)
    const float w20 = __ldg(&w2[0]), w21 = __ldg(&w2[1]), w22 = __ldg(&w2[2]);
    const float B2  = __ldg(b2);
    float pa = __shfl_sync(FULL, p, (3 * lane)     & 31);
    float pb = __shfl_sync(FULL, p, (3 * lane + 1) & 31);
    float pc = __shfl_sync(FULL, p, (3 * lane + 2) & 31);
    float q = fmaxf(fmaf(w20, pa, fmaf(w21, pb, fmaf(w22, pc, B2))), 0.0f);

    // ---- maxpool k=3 s=3 pad=1 (10 -> 4), relu no-op  (lanes 0..3 produce r)
    float qm = __shfl_sync(FULL, q, (3 * lane - 1) & 31);
    float q0 = __shfl_sync(FULL, q, (3 * lane)     & 31);
    float qp = __shfl_sync(FULL, q, (3 * lane + 1) & 31);
    float r;
    if (lane == 0)      r = fmaxf(q0, qp);        // window {-1(pad),0,1}
    else if (lane == 3) r = fmaxf(qm, q0);        // window {8,9,10(pad)}
    else                r = fmaxf(fmaxf(qm, q0), qp);

    // ---- conv3: K=4 s=1 (4 -> 1), relu -> feat
    float r0 = __shfl_sync(FULL, r, 0);
    float r1 = __shfl_sync(FULL, r, 1);
    float r2 = __shfl_sync(FULL, r, 2);
    float r3 = __shfl_sync(FULL, r, 3);
    if (lane == 0) {
        float f = __ldg(b3);
        f = fmaf(__ldg(&w3[0]), r0, f);
        f = fmaf(__ldg(&w3[1]), r1, f);
        f = fmaf(__ldg(&w3[2]), r2, f);
        f = fmaf(__ldg(&w3[3]), r3, f);
        g_feat[row] = fmaxf(f, 0.0f);
    }
}

// logits = feat @ cls_w.T + cls_b ; softmax over 3 classes. One block per batch.
__global__ __launch_bounds__(256) void head_kernel(
    const float* __restrict__ cw,   // [3,1024]
    const float* __restrict__ cb,   // [3]
    float* __restrict__ out)        // [64,3]
{
    const int b = blockIdx.x;
    const float* f = g_feat + b * 1024;

    float a0 = 0.f, a1 = 0.f, a2 = 0.f;
    for (int n = threadIdx.x; n < 1024; n += 256) {
        float v = f[n];
        a0 = fmaf(v, __ldg(&cw[n]),        a0);
        a1 = fmaf(v, __ldg(&cw[1024 + n]), a1);
        a2 = fmaf(v, __ldg(&cw[2048 + n]), a2);
    }
    #pragma unroll
    for (int o = 16; o > 0; o >>= 1) {
        a0 += __shfl_xor_sync(FULL, a0, o);
        a1 += __shfl_xor_sync(FULL, a1, o);
        a2 += __shfl_xor_sync(FULL, a2, o);
    }
    __shared__ float s[8][3];
    if ((threadIdx.x & 31) == 0) {
        int w = threadIdx.x >> 5;
        s[w][0] = a0; s[w][1] = a1; s[w][2] = a2;
    }
    __syncthreads();
    if (threadIdx.x == 0) {
        float l0 = __ldg(&cb[0]), l1 = __ldg(&cb[1]), l2 = __ldg(&cb[2]);
        #pragma unroll
        for (int w = 0; w < 8; w++) { l0 += s[w][0]; l1 += s[w][1]; l2 += s[w][2]; }
        float m  = fmaxf(l0, fmaxf(l1, l2));
        float e0 = expf(l0 - m), e1 = expf(l1 - m), e2 = expf(l2 - m);
        float inv = 1.0f / (e0 + e1 + e2);
        out[b * 3 + 0] = e0 * inv;
        out[b * 3 + 1] = e1 * inv;
        out[b * 3 + 2] = e2 * inv;
    }
}

extern "C" void kernel_launch(void* const* d_in, const int* in_sizes, int n_in,
                              void* d_out, int out_size)
{
    // metadata order: input, conv1_w, conv1_b, conv2_w, conv2_b, conv3_w,
    // conv3_b, gcn1_w, gcn1_b, gcn2_w, gcn2_b, cls_w, cls_b  (gcn* are dead)
    const float* x   = (const float*)d_in[0];
    const float* w1  = (const float*)d_in[1];
    const float* b1  = (const float*)d_in[2];
    const float* w2  = (const float*)d_in[3];
    const float* b2  = (const float*)d_in[4];
    const float* w3  = (const float*)d_in[5];
    const float* b3  = (const float*)d_in[6];
    const float* cw  = (const float*)d_in[11];
    const float* cb  = (const float*)d_in[12];
    float* out = (float*)d_out;

    // 64*1024 rows, 8 rows per block
    conv_chain_kernel<<<8192, 256>>>(x, w1, b1, w2, b2, w3, b3);
    head_kernel<<<64, 256>>>(cw, cb, out);
}

// round 2
// speedup vs baseline: 1.0627x; 1.0627x over previous
#include <cuda_runtime.h>

#define FULL 0xFFFFFFFFu

// feat[b][n] scratch (64*1024 floats). __device__ global = allowed scratch.
__device__ float g_feat[64 * 1024];

__global__ __launch_bounds__(256) void conv_chain_kernel(
    const float* __restrict__ x,
    const float* __restrict__ w1, const float* __restrict__ b1,
    const float* __restrict__ w2, const float* __restrict__ b2,
    const float* __restrict__ w3, const float* __restrict__ b3)
{
    // 8 warps per block, one row (b,n) per warp. Small smem only for the
    // 150->30 maxpool redistribution (stride-5 reads are conflict-free).
    __shared__ float sm[8][152];

    const int warp = threadIdx.x >> 5;
    const int lane = threadIdx.x & 31;
    const int row  = blockIdx.x * 8 + warp;   // row in [0, 65536)

    const float4* X4 = reinterpret_cast<const float4*>(x + (size_t)row * 1200);

    // ---- conv1: K=10, stride=8, pad=1, out length 150, relu
    // Output j (= 32*it + lane) window: x[8j-1 .. 8j+8].
    // Per-lane direct loads: A0 = x[8j..8j+3], A1 = x[8j+4..8j+7].
    // Across the warp each LDG.128 covers 1024 contiguous bytes (8 lines).
    float4 A0[5], A1[5];
    #pragma unroll
    for (int it = 0; it < 5; it++) {
        int j  = it * 32 + lane;
        int jj = j < 150 ? j : 149;          // clamp (it==4 lanes 22..31 idle)
        A0[it] = X4[2 * jj];
        A1[it] = X4[2 * jj + 1];
    }

    float W1[10];
    #pragma unroll
    for (int k = 0; k < 10; k++) W1[k] = __ldg(&w1[k]);
    const float B1 = __ldg(b1);

    float y[5];
    float carry = 0.0f;                      // x[8j-1] carry (x[-1] = left pad)
    #pragma unroll
    for (int it = 0; it < 5; it++) {
        // x[8j-1] = elem 8(j-1)+7 = previous lane's A1.w
        float xm1 = __shfl_up_sync(FULL, A1[it].w, 1);
        if (lane == 0) xm1 = carry;
        carry = __shfl_sync(FULL, A1[it].w, 31);

        // x[8j+8] = elem 8(j+1) = next lane's A0.x; lane 31 takes next iter's
        // lane-0 A0.x. j==149 needs the right pad (0).
        float nxt  = (it < 4) ? __shfl_sync(FULL, A0[it + 1].x, 0) : 0.0f;
        float a2   = __shfl_down_sync(FULL, A0[it].x, 1);
        if (lane == 31) a2 = nxt;
        int j = it * 32 + lane;
        if (j == 149) a2 = 0.0f;             // right pad

        float v = B1;
        v = fmaf(W1[0], xm1,      v);
        v = fmaf(W1[1], A0[it].x, v);
        v = fmaf(W1[2], A0[it].y, v);
        v = fmaf(W1[3], A0[it].z, v);
        v = fmaf(W1[4], A0[it].w, v);
        v = fmaf(W1[5], A1[it].x, v);
        v = fmaf(W1[6], A1[it].y, v);
        v = fmaf(W1[7], A1[it].z, v);
        v = fmaf(W1[8], A1[it].w, v);
        v = fmaf(W1[9], a2,       v);
        y[it] = fmaxf(v, 0.0f);
    }

    // ---- stash y1 (150 vals) in tiny smem for the stride-5 pool gather
    float* S = sm[warp];
    #pragma unroll
    for (int it = 0; it < 5; it++) {
        int j = it * 32 + lane;
        if (j < 150) S[j] = y[it];
    }
    __syncwarp();

    // ---- maxpool k=5 s=5 (150 -> 30); relu no-op (inputs >= 0)
    float p = 0.0f;
    if (lane < 30) {
        p = S[5 * lane];
        #pragma unroll
        for (int k = 1; k < 5; k++) p = fmaxf(p, S[5 * lane + k]);
    }

    // ---- conv2: K=3 s=3 (30 -> 10), relu  (lanes 0..9 produce q)
    const float w20 = __ldg(&w2[0]), w21 = __ldg(&w2[1]), w22 = __ldg(&w2[2]);
    const float B2  = __ldg(b2);
    float pa = __shfl_sync(FULL, p, (3 * lane)     & 31);
    float pb = __shfl_sync(FULL, p, (3 * lane + 1) & 31);
    float pc = __shfl_sync(FULL, p, (3 * lane + 2) & 31);
    float q = fmaxf(fmaf(w20, pa, fmaf(w21, pb, fmaf(w22, pc, B2))), 0.0f);

    // ---- maxpool k=3 s=3 pad=1 (10 -> 4); relu no-op  (lanes 0..3 produce r)
    float qm = __shfl_sync(FULL, q, (3 * lane - 1) & 31);
    float q0 = __shfl_sync(FULL, q, (3 * lane)     & 31);
    float qp = __shfl_sync(FULL, q, (3 * lane + 1) & 31);
    float r;
    if (lane == 0)      r = fmaxf(q0, qp);        // window {-1(pad),0,1}
    else if (lane == 3) r = fmaxf(qm, q0);        // window {8,9,10(pad)}
    else                r = fmaxf(fmaxf(qm, q0), qp);

    // ---- conv3: K=4 s=1 (4 -> 1), relu -> feat
    float r0 = __shfl_sync(FULL, r, 0);
    float r1 = __shfl_sync(FULL, r, 1);
    float r2 = __shfl_sync(FULL, r, 2);
    float r3 = __shfl_sync(FULL, r, 3);
    if (lane == 0) {
        float f = __ldg(b3);
        f = fmaf(__ldg(&w3[0]), r0, f);
        f = fmaf(__ldg(&w3[1]), r1, f);
        f = fmaf(__ldg(&w3[2]), r2, f);
        f = fmaf(__ldg(&w3[3]), r3, f);
        g_feat[row] = fmaxf(f, 0.0f);
    }
}

// logits = feat @ cls_w.T + cls_b ; softmax over 3 classes. One block per batch.
// Each thread handles 4 nodes via float4 (256 threads * 4 = 1024 nodes).
__global__ __launch_bounds__(256) void head_kernel(
    const float* __restrict__ cw,   // [3,1024]
    const float* __restrict__ cb,   // [3]
    float* __restrict__ out)        // [64,3]
{
    const int b = blockIdx.x;
    const int t = threadIdx.x;
    const float4* f4 = reinterpret_cast<const float4*>(g_feat + b * 1024);
    const float4* c0 = reinterpret_cast<const float4*>(cw);
    const float4* c1 = reinterpret_cast<const float4*>(cw + 1024);
    const float4* c2 = reinterpret_cast<const float4*>(cw + 2048);

    float4 fv = f4[t];
    float4 w0 = c0[t], w1 = c1[t], w2 = c2[t];

    float a0 = fv.x * w0.x + fv.y * w0.y + fv.z * w0.z + fv.w * w0.w;
    float a1 = fv.x * w1.x + fv.y * w1.y + fv.z * w1.z + fv.w * w1.w;
    float a2 = fv.x * w2.x + fv.y * w2.y + fv.z * w2.z + fv.w * w2.w;

    #pragma unroll
    for (int o = 16; o > 0; o >>= 1) {
        a0 += __shfl_xor_sync(FULL, a0, o);
        a1 += __shfl_xor_sync(FULL, a1, o);
        a2 += __shfl_xor_sync(FULL, a2, o);
    }
    __shared__ float s[8][3];
    if ((t & 31) == 0) {
        int w = t >> 5;
        s[w][0] = a0; s[w][1] = a1; s[w][2] = a2;
    }
    __syncthreads();
    if (t == 0) {
        float l0 = __ldg(&cb[0]), l1 = __ldg(&cb[1]), l2 = __ldg(&cb[2]);
        #pragma unroll
        for (int w = 0; w < 8; w++) { l0 += s[w][0]; l1 += s[w][1]; l2 += s[w][2]; }
        float m  = fmaxf(l0, fmaxf(l1, l2));
        float e0 = expf(l0 - m), e1 = expf(l1 - m), e2 = expf(l2 - m);
        float inv = 1.0f / (e0 + e1 + e2);
        out[b * 3 + 0] = e0 * inv;
        out[b * 3 + 1] = e1 * inv;
        out[b * 3 + 2] = e2 * inv;
    }
}

extern "C" void kernel_launch(void* const* d_in, const int* in_sizes, int n_in,
                              void* d_out, int out_size)
{
    // metadata order: input, conv1_w, conv1_b, conv2_w, conv2_b, conv3_w,
    // conv3_b, gcn1_w, gcn1_b, gcn2_w, gcn2_b, cls_w, cls_b  (gcn* are dead)
    const float* x   = (const float*)d_in[0];
    const float* w1  = (const float*)d_in[1];
    const float* b1  = (const float*)d_in[2];
    const float* w2  = (const float*)d_in[3];
    const float* b2  = (const float*)d_in[4];
    const float* w3  = (const float*)d_in[5];
    const float* b3  = (const float*)d_in[6];
    const float* cw  = (const float*)d_in[11];
    const float* cb  = (const float*)d_in[12];
    float* out = (float*)d_out;

    conv_chain_kernel<<<8192, 256>>>(x, w1, b1, w2, b2, w3, b3);
    head_kernel<<<64, 256>>>(cw, cb, out);
}